// round 1
// baseline (speedup 1.0000x reference)
#include <cuda_runtime.h>

#define BB 512
#define TT 512
#define NS 64

__global__ __launch_bounds__(64) void crf_kernel(
    const float* __restrict__ inputs,   // [B,T,N]
    const float* __restrict__ trans,    // [N,N]
    const int*   __restrict__ tags,     // [B,T]
    const int*   __restrict__ lens,     // [B]
    float*       __restrict__ out,      // [B] ll, then [N*N] trans copy
    int write_trans)
{
    const int b    = blockIdx.x;
    const int j    = threadIdx.x;   // state index 0..63
    const int w    = j >> 5;        // warp id (0/1)
    const int lane = j & 31;

    __shared__ float p_buf[2][NS];
    __shared__ float m_buf[2][2];
    __shared__ float red[2];

    // optional: blocks 0..63 also copy transition_params to output tail
    if (write_trans && b < NS) {
        out[BB + b * NS + j] = trans[b * NS + j];
    }

    const int len  = lens[b];
    const int last = (len - 1) > 0 ? (len - 1) : 0;

    // ---------------- sequence score ----------------
    float sc = 0.f;
    const int* tg = tags + (size_t)b * TT;
    const float* in_b = inputs + (size_t)b * TT * NS;
    for (int t = j; t < TT; t += NS) {
        if (t < len) {
            int yt = tg[t];
            sc += __ldg(&in_b[(size_t)t * NS + yt]);
            if (t >= 1) sc += __ldg(&trans[tg[t - 1] * NS + yt]);
        }
    }
    #pragma unroll
    for (int o = 16; o; o >>= 1) sc += __shfl_xor_sync(0xffffffffu, sc, o);
    if (lane == 0) red[w] = sc;
    __syncthreads();
    const float seq_score = red[0] + red[1];
    __syncthreads();

    // ---------------- E column into registers ----------------
    float e[NS];
    #pragma unroll
    for (int i = 0; i < NS; ++i)
        e[i] = __expf(__ldg(&trans[i * NS + j]));

    // ---------------- forward recurrence ----------------
    float alpha = in_b[j];  // t = 0

    // emit prefetch pipeline (depth 4)
    float pf0 = 0.f, pf1 = 0.f, pf2 = 0.f, pf3 = 0.f;
    if (1 <= last) pf0 = in_b[1 * NS + j];
    if (2 <= last) pf1 = in_b[2 * NS + j];
    if (3 <= last) pf2 = in_b[3 * NS + j];
    if (4 <= last) pf3 = in_b[4 * NS + j];

    int buf = 0;
    for (int t = 1; t <= last; ++t) {
        // per-warp reference (lane 0's alpha); spread of alpha is bounded (~19)
        const float mw = __shfl_sync(0xffffffffu, alpha, 0);
        const float pj = __expf(alpha - mw);
        p_buf[buf][j] = pj;
        if (lane == 0) m_buf[buf][w] = mw;
        __syncthreads();

        const float m0 = m_buf[buf][0];
        const float m1 = m_buf[buf][1];

        const float4* p4 = (const float4*)p_buf[buf];
        float a0 = 0.f, a1 = 0.f, a2 = 0.f, a3 = 0.f;  // i < 32  (scale m0)
        float b0 = 0.f, b1 = 0.f, b2 = 0.f, b3 = 0.f;  // i >= 32 (scale m1)
        #pragma unroll
        for (int i4 = 0; i4 < 8; ++i4) {
            float4 v = p4[i4];
            a0 += v.x * e[4 * i4 + 0];
            a1 += v.y * e[4 * i4 + 1];
            a2 += v.z * e[4 * i4 + 2];
            a3 += v.w * e[4 * i4 + 3];
        }
        #pragma unroll
        for (int i4 = 8; i4 < 16; ++i4) {
            float4 v = p4[i4];
            b0 += v.x * e[4 * i4 + 0];
            b1 += v.y * e[4 * i4 + 1];
            b2 += v.z * e[4 * i4 + 2];
            b3 += v.w * e[4 * i4 + 3];
        }
        const float acc = ((a0 + a1) + (a2 + a3))
                        + __expf(m1 - m0) * ((b0 + b1) + (b2 + b3));

        const float emit = pf0;
        pf0 = pf1; pf1 = pf2; pf2 = pf3;
        const int tn = t + 4;
        if (tn <= last) pf3 = in_b[(size_t)tn * NS + j];

        alpha = emit + m0 + __logf(acc);
        buf ^= 1;
    }

    // ---------------- final logsumexp over states ----------------
    float mx = alpha;
    #pragma unroll
    for (int o = 16; o; o >>= 1)
        mx = fmaxf(mx, __shfl_xor_sync(0xffffffffu, mx, o));
    if (lane == 0) red[w] = mx;
    __syncthreads();
    mx = fmaxf(red[0], red[1]);
    __syncthreads();

    float s = __expf(alpha - mx);
    #pragma unroll
    for (int o = 16; o; o >>= 1)
        s += __shfl_xor_sync(0xffffffffu, s, o);
    if (lane == 0) red[w] = s;
    __syncthreads();
    s = red[0] + red[1];

    if (j == 0) out[b] = seq_score - (mx + __logf(s));
}

extern "C" void kernel_launch(void* const* d_in, const int* in_sizes, int n_in,
                              void* d_out, int out_size) {
    const float* inputs = (const float*)d_in[0];   // [B,T,N] f32
    const float* trans  = (const float*)d_in[1];   // [N,N]   f32
    const int*   tags   = (const int*)d_in[2];     // [B,T]   i32
    const int*   lens   = (const int*)d_in[3];     // [B]     i32
    float* out = (float*)d_out;

    const int write_trans = (out_size >= BB + NS * NS) ? 1 : 0;
    crf_kernel<<<BB, NS>>>(inputs, trans, tags, lens, out, write_trans);
}

// round 2
// speedup vs baseline: 2.1071x; 2.1071x over previous
#include <cuda_runtime.h>

#define BB 512
#define TT 512
#define NS 64

// 2 full-precision fp32 FMAs per instruction (sm_103a packed pipe)
#define FMA2(acc, p, e) \
    asm("fma.rn.f32x2 %0, %1, %2, %0;" : "+l"(acc) : "l"(p), "l"(e))
#define UNPACK2(lo, hi, v) \
    asm("mov.b64 {%0, %1}, %2;" : "=r"(lo), "=r"(hi) : "l"(v))

__device__ int d_perm[BB];

// Rank batches by sequence length (descending) so the longest chains start
// first, land on distinct SMs, and run the tail uncontended.
__global__ void rank_kernel(const int* __restrict__ lens) {
    __shared__ int L[BB];
    const int b = threadIdx.x;
    L[b] = lens[b];
    __syncthreads();
    const int myl = L[b];
    int r = 0;
    #pragma unroll 8
    for (int i = 0; i < BB; ++i) {
        const int li = L[i];
        r += (li > myl) || (li == myl && i < b);
    }
    d_perm[r] = b;
}

__global__ __launch_bounds__(64) void crf_kernel(
    const float* __restrict__ inputs,   // [B,T,N]
    const float* __restrict__ trans,    // [N,N]
    const int*   __restrict__ tags,    // [B,T]
    const int*   __restrict__ lens,    // [B]
    float*       __restrict__ out,     // [B] ll, then [N*N] trans copy
    int write_trans)
{
    const int bb   = blockIdx.x;
    const int b    = d_perm[bb];
    const int j    = threadIdx.x;   // state index 0..63
    const int w    = j >> 5;
    const int lane = j & 31;

    __shared__ __align__(16) float s_buf[2][NS];
    __shared__ float red[2];

    if (write_trans && bb < NS) {
        out[BB + bb * NS + j] = trans[bb * NS + j];
    }

    const int len  = lens[b];
    const int last = (len - 1) > 0 ? (len - 1) : 0;

    const int* tg = tags + (size_t)b * TT;
    const float* in_b = inputs + (size_t)b * TT * NS;

    // ---------------- sequence score ----------------
    float sc = 0.f;
    for (int t = j; t < TT; t += NS) {
        if (t < len) {
            int yt = tg[t];
            sc += __ldg(&in_b[(size_t)t * NS + yt]);
            if (t >= 1) sc += __ldg(&trans[tg[t - 1] * NS + yt]);
        }
    }
    #pragma unroll
    for (int o = 16; o; o >>= 1) sc += __shfl_xor_sync(0xffffffffu, sc, o);
    if (lane == 0) red[w] = sc;
    __syncthreads();
    const float seq_score = red[0] + red[1];
    __syncthreads();

    // ---------------- E column j, packed into f32x2 pairs over i ----------------
    unsigned long long e2[NS / 2];
    #pragma unroll
    for (int k = 0; k < NS / 2; ++k) {
        unsigned lo = __float_as_uint(__expf(__ldg(&trans[(2 * k) * NS + j])));
        unsigned hi = __float_as_uint(__expf(__ldg(&trans[(2 * k + 1) * NS + j])));
        asm("mov.b64 %0, {%1, %2};" : "=l"(e2[k]) : "r"(lo), "r"(hi));
    }

    // ---------------- forward recurrence, scaled linear space ----------------
    // s_j(t) = exp(alpha_j(t) - M_t);  M tracked off the critical path.
    const float emit0_0 = __ldg(&in_b[0]);
    float M = emit0_0;
    float s_cur = __expf(in_b[j] - emit0_0);
    s_buf[0][j] = s_cur;

    // prefetch pe (= exp(emit_j - emit0)) and emit0 for steps t=1..6 (depth 6)
    float pe0 = 1.f, pe1 = 1.f, pe2 = 1.f, pe3 = 1.f, pe4 = 1.f, pe5 = 1.f;
    float me0 = 0.f, me1 = 0.f, me2 = 0.f, me3 = 0.f, me4 = 0.f, me5 = 0.f;
    {
        float e0, em;
        if (1 <= last) { e0 = __ldg(&in_b[1 * NS]); em = __ldg(&in_b[1 * NS + j]); pe0 = __expf(em - e0); me0 = e0; }
        if (2 <= last) { e0 = __ldg(&in_b[2 * NS]); em = __ldg(&in_b[2 * NS + j]); pe1 = __expf(em - e0); me1 = e0; }
        if (3 <= last) { e0 = __ldg(&in_b[3 * NS]); em = __ldg(&in_b[3 * NS + j]); pe2 = __expf(em - e0); me2 = e0; }
        if (4 <= last) { e0 = __ldg(&in_b[4 * NS]); em = __ldg(&in_b[4 * NS + j]); pe3 = __expf(em - e0); me3 = e0; }
        if (5 <= last) { e0 = __ldg(&in_b[5 * NS]); em = __ldg(&in_b[5 * NS + j]); pe4 = __expf(em - e0); me4 = e0; }
        if (6 <= last) { e0 = __ldg(&in_b[6 * NS]); em = __ldg(&in_b[6 * NS + j]); pe5 = __expf(em - e0); me5 = e0; }
    }

    int buf = 0;
    for (int t = 1; t <= last; ++t) {
        __syncthreads();

        // issue next prefetch early (independent of the dot)
        const float pe_c = pe0, me_c = me0;
        pe0 = pe1; me0 = me1; pe1 = pe2; me1 = me2; pe2 = pe3; me2 = me3;
        pe3 = pe4; me3 = me4; pe4 = pe5; me4 = me5;
        const int tn = t + 6;
        if (tn <= last) {
            const float e0 = __ldg(&in_b[(size_t)tn * NS]);
            const float em = __ldg(&in_b[(size_t)tn * NS + j]);
            pe5 = __expf(em - e0);
            me5 = e0;
        }

        const float s0 = s_buf[buf][0];          // broadcast scalar LDS
        const float r_inv = __fdividef(1.f, s0); // MUFU, overlaps the dot
        M += me_c + __logf(s0);                  // off the s-chain

        const ulonglong2* p4 = (const ulonglong2*)s_buf[buf];
        unsigned long long a0 = 0ull, a1 = 0ull, a2 = 0ull, a3 = 0ull;
        #pragma unroll
        for (int m = 0; m < 16; m += 4) {
            ulonglong2 va = p4[m + 0];
            ulonglong2 vb = p4[m + 1];
            ulonglong2 vc = p4[m + 2];
            ulonglong2 vd = p4[m + 3];
            FMA2(a0, va.x, e2[2 * m + 0]); FMA2(a1, va.y, e2[2 * m + 1]);
            FMA2(a2, vb.x, e2[2 * m + 2]); FMA2(a3, vb.y, e2[2 * m + 3]);
            FMA2(a0, vc.x, e2[2 * m + 4]); FMA2(a1, vc.y, e2[2 * m + 5]);
            FMA2(a2, vd.x, e2[2 * m + 6]); FMA2(a3, vd.y, e2[2 * m + 7]);
        }
        unsigned l0, h0, l1, h1, l2, h2, l3, h3;
        UNPACK2(l0, h0, a0); UNPACK2(l1, h1, a1);
        UNPACK2(l2, h2, a2); UNPACK2(l3, h3, a3);
        const float acc =
            ((__uint_as_float(l0) + __uint_as_float(h0)) +
             (__uint_as_float(l1) + __uint_as_float(h1))) +
            ((__uint_as_float(l2) + __uint_as_float(h2)) +
             (__uint_as_float(l3) + __uint_as_float(h3)));

        s_cur = acc * (pe_c * r_inv);
        s_buf[buf ^ 1][j] = s_cur;
        buf ^= 1;
    }

    // alpha_j(last) = log(s_j) + M
    const float alpha = __logf(s_cur) + M;

    // ---------------- final logsumexp over states ----------------
    float mx = alpha;
    #pragma unroll
    for (int o = 16; o; o >>= 1)
        mx = fmaxf(mx, __shfl_xor_sync(0xffffffffu, mx, o));
    if (lane == 0) red[w] = mx;
    __syncthreads();
    mx = fmaxf(red[0], red[1]);
    __syncthreads();

    float s = __expf(alpha - mx);
    #pragma unroll
    for (int o = 16; o; o >>= 1)
        s += __shfl_xor_sync(0xffffffffu, s, o);
    if (lane == 0) red[w] = s;
    __syncthreads();
    s = red[0] + red[1];

    if (j == 0) out[b] = seq_score - (mx + __logf(s));
}

extern "C" void kernel_launch(void* const* d_in, const int* in_sizes, int n_in,
                              void* d_out, int out_size) {
    const float* inputs = (const float*)d_in[0];   // [B,T,N] f32
    const float* trans  = (const float*)d_in[1];   // [N,N]   f32
    const int*   tags   = (const int*)d_in[2];     // [B,T]   i32
    const int*   lens   = (const int*)d_in[3];     // [B]     i32
    float* out = (float*)d_out;

    const int write_trans = (out_size >= BB + NS * NS) ? 1 : 0;
    rank_kernel<<<1, BB>>>(lens);
    crf_kernel<<<BB, NS>>>(inputs, trans, tags, lens, out, write_trans);
}